// round 10
// baseline (speedup 1.0000x reference)
#include <cuda_runtime.h>
#include <cstdint>

// ---------------------------------------------------------------------------
// GMP_34196529611440 : generalized memory polynomial, single fused kernel.
// Round 9: occupancy push. ITER=2, TPB=256, __launch_bounds__(256,5)
//          -> 51-reg cap, 5 CTAs/SM, 62% theoretical occupancy.
//   * Horner form (k=0 constants folded -> zero add2).
//   * padded shared tile pad(i)=i+(i>>1): lane stride 6 words, conflict-free.
//   * register p-window holds only hot sites j=1..8; j=0/9 read from shared.
// ---------------------------------------------------------------------------

typedef unsigned long long u64;

__device__ __forceinline__ u64 fma2(u64 a, u64 b, u64 c) {
    u64 d;
    asm("fma.rn.f32x2 %0, %1, %2, %3;" : "=l"(d) : "l"(a), "l"(b), "l"(c));
    return d;
}
__device__ __forceinline__ u64 pack2(float x, float y) {
    u64 r;
    asm("mov.b64 %0, {%1, %2};" : "=l"(r) : "f"(x), "f"(y));
    return r;
}
__device__ __forceinline__ void unpack2(u64 v, float& x, float& y) {
    asm("mov.b64 {%0, %1}, %2;" : "=f"(x), "=f"(y) : "l"(v));
}
__device__ __forceinline__ float sqrt_approx(float s) {
    float r;
    asm("sqrt.approx.f32 %0, %1;" : "=f"(r) : "f"(s));
    return r;
}

constexpr int ITER = 2;            // consecutive samples per thread
constexpr int TPB  = 256;
constexpr int SPB  = TPB * ITER;   // 512 (divides N = 2^20)
constexpr int TILE = SPB + 12;     // samples blockStart-5 .. +6
// pad(i) = i + (i>>1)
constexpr int PTILE = (TILE - 1) + ((TILE - 1) >> 1) + 1;

// shared coefficient layout (complex {re,im} as u64):
//   [0..3]    c0tot[l]   (all k=0 constant terms folded per l)
//   [4..19]   E[l*4 + (k-1)]  k=1..4   (a merged with b/c m=0 terms)
//   [20..46]  B[l*9 + (m-1)*3 + (k-1)]  l<3, m=1..3, k=1..3
//   [47..73]  C[...same...]
constexpr int NCOEF = 74;

__global__ __launch_bounds__(TPB, 5)
void gmp_kernel(const float* __restrict__ xre, const float* __restrict__ xim,
                const float* __restrict__ a_re, const float* __restrict__ a_im,
                const float* __restrict__ b_re, const float* __restrict__ b_im,
                const float* __restrict__ c_re, const float* __restrict__ c_im,
                float* __restrict__ out, int N) {
    __shared__ u64 sP[PTILE];      // {p, p}   duplicated |x|
    __shared__ u64 sX[PTILE];      // {re, im}
    __shared__ float2 scoef[NCOEF];

    const int tid = threadIdx.x;
    const int blockStart = blockIdx.x * SPB;

    // ---- per-block coefficient merge (threads 0..73), cheap one-time work
    if (tid < NCOEF) {
        float re, im;
        if (tid < 4) {                 // c0tot[l]
            int l = tid;
            re = a_re[l]; im = a_im[l];
            if (l < 3) {
#pragma unroll
                for (int m = 0; m < 4; ++m) {
                    re += b_re[l * 4 + m] + c_re[l * 4 + m];
                    im += b_im[l * 4 + m] + c_im[l * 4 + m];
                }
            }
        } else if (tid < 20) {         // E[l][k], k=1..4
            int e = tid - 4, l = e >> 2, k = (e & 3) + 1;
            re = a_re[k * 4 + l]; im = a_im[k * 4 + l];
            if (l < 3 && k < 4) {      // merge b/c m=0
                int src = (k * 3 + l) * 4;
                re += b_re[src] + c_re[src];
                im += b_im[src] + c_im[src];
            }
        } else if (tid < 47) {         // B
            int e = tid - 20, l = e / 9, r9 = e % 9, m = r9 / 3 + 1, k = r9 % 3 + 1;
            int src = (k * 3 + l) * 4 + m;
            re = b_re[src]; im = b_im[src];
        } else {                       // C
            int e = tid - 47, l = e / 9, r9 = e % 9, m = r9 / 3 + 1, k = r9 % 3 + 1;
            int src = (k * 3 + l) * 4 + m;
            re = c_re[src]; im = c_im[src];
        }
        scoef[tid] = make_float2(re, im);
    }

    // ---- cooperative tile load: each sample once, |x| once, padded stores
#pragma unroll
    for (int s = tid; s < TILE; s += TPB) {
        int g = blockStart - 5 + s;
        g = max(g, 0);
        g = min(g, N - 1);
        float r = xre[g];
        float i = xim[g];
        float p = sqrt_approx(fmaf(r, r, i * i));
        int ps = s + (s >> 1);
        sX[ps] = pack2(r, i);
        sP[ps] = pack2(p, p);
    }
    __syncthreads();

    const u64* sc = reinterpret_cast<const u64*>(scoef);
    const int pb3 = tid * 3;            // pad(tid*2)
    const int n0 = blockStart + tid * ITER;

    // window j = 0..9 corresponds to sample n0 + j - 5; padded index:
    //   i = 2*tid + j  ->  pad(i) = 3*tid + j + (j>>1)   (2*tid even)
#define PIDX(j) (pb3 + (j) + ((j) >> 1))

    // hot |x| window in registers: j = 1..8 (8 u64); j=0,9 read from shared
    u64 ppr[8];
#pragma unroll
    for (int j = 1; j <= 8; ++j) ppr[j - 1] = sP[PIDX(j)];
#define GETP(j) (((j) >= 1 && (j) <= 8) ? ppr[(j) - 1] : sP[PIDX(j)])

    float yr[ITER], yi[ITER];
#pragma unroll
    for (int it = 0; it < ITER; ++it) { yr[it] = 0.f; yi[it] = 0.f; }

#pragma unroll
    for (int l = 0; l < 4; ++l) {
        u64 wl[ITER];
        {
            const u64 c0 = sc[l];
#pragma unroll
            for (int it = 0; it < ITER; ++it) wl[it] = c0;
        }
        // E (deg 4): w += (((e4 p + e3) p + e2) p + e1) p   at p[n+it-l]
        {
            const u64 e1 = sc[4 + l * 4 + 0], e2 = sc[4 + l * 4 + 1],
                      e3 = sc[4 + l * 4 + 2], e4 = sc[4 + l * 4 + 3];
#pragma unroll
            for (int it = 0; it < ITER; ++it) {
                const u64 p = GETP(it - l + 5);
                u64 q = fma2(e4, p, e3);
                q = fma2(q, p, e2);
                q = fma2(q, p, e1);
                wl[it] = fma2(q, p, wl[it]);
            }
        }
        if (l < 3) {
#pragma unroll
            for (int m = 1; m < 4; ++m) {   // B at p[n+it-l-m]
                const int bb = 20 + l * 9 + (m - 1) * 3;
                const u64 b1 = sc[bb + 0], b2 = sc[bb + 1], b3 = sc[bb + 2];
#pragma unroll
                for (int it = 0; it < ITER; ++it) {
                    const u64 p = GETP(it - l - m + 5);
                    u64 q = fma2(b3, p, b2);
                    q = fma2(q, p, b1);
                    wl[it] = fma2(q, p, wl[it]);
                }
            }
#pragma unroll
            for (int m = 1; m < 4; ++m) {   // C at p[n+it-l+m]
                const int cb = 47 + l * 9 + (m - 1) * 3;
                const u64 c1 = sc[cb + 0], c2 = sc[cb + 1], c3 = sc[cb + 2];
#pragma unroll
                for (int it = 0; it < ITER; ++it) {
                    const u64 p = GETP(it - l + m + 5);
                    u64 q = fma2(c3, p, c2);
                    q = fma2(q, p, c1);
                    wl[it] = fma2(q, p, wl[it]);
                }
            }
        }
        // combine: y[n+it] += x[n+it-l] * w_l   (complex; x from padded shared)
#pragma unroll
        for (int it = 0; it < ITER; ++it) {
            float vr, vi;
            unpack2(wl[it], vr, vi);
            float r, i;
            unpack2(sX[PIDX(it - l + 5)], r, i);
            yr[it] = fmaf(r, vr, yr[it]);
            yr[it] = fmaf(-i, vi, yr[it]);
            yi[it] = fmaf(r, vi, yi[it]);
            yi[it] = fmaf(i, vr, yi[it]);
        }
    }
#undef GETP
#undef PIDX

    // n0 is even -> 8B-aligned float2 stores; SPB divides N
    if (n0 + ITER <= N) {
        *reinterpret_cast<float2*>(out + n0)     = make_float2(yr[0], yr[1]);
        *reinterpret_cast<float2*>(out + N + n0) = make_float2(yi[0], yi[1]);
    } else {
#pragma unroll
        for (int it = 0; it < ITER; ++it) {
            int n = n0 + it;
            if (n < N) { out[n] = yr[it]; out[N + n] = yi[it]; }
        }
    }
}

extern "C" void kernel_launch(void* const* d_in, const int* in_sizes, int n_in,
                              void* d_out, int out_size) {
    const float* x_re = (const float*)d_in[0];
    const float* x_im = (const float*)d_in[1];
    const float* a_re = (const float*)d_in[2];
    const float* a_im = (const float*)d_in[3];
    const float* b_re = (const float*)d_in[4];
    const float* b_im = (const float*)d_in[5];
    const float* c_re = (const float*)d_in[6];
    const float* c_im = (const float*)d_in[7];
    float* out = (float*)d_out;
    const int N = in_sizes[0];

    const int grid = (N + SPB - 1) / SPB;
    gmp_kernel<<<grid, TPB>>>(x_re, x_im, a_re, a_im, b_re, b_im,
                              c_re, c_im, out, N);
}

// round 13
// speedup vs baseline: 1.1081x; 1.1081x over previous
#include <cuda_runtime.h>
#include <cstdint>

// ---------------------------------------------------------------------------
// GMP_34196529611440 : generalized memory polynomial, single fused kernel.
// Round 11 = R8 (ITER=4, Horner, padded tile) with:
//   * TPB=128, __launch_bounds__(128,9)  -> 56-reg cap, 36 warps/SM (56% occ)
//   * p-window registers trimmed to hot sites j=1..10 (j=0/11 from shared)
//   * coefficients in 16B-aligned groups, loaded via ld.shared.v2.u64
// ---------------------------------------------------------------------------

typedef unsigned long long u64;

__device__ __forceinline__ u64 fma2(u64 a, u64 b, u64 c) {
    u64 d;
    asm("fma.rn.f32x2 %0, %1, %2, %3;" : "=l"(d) : "l"(a), "l"(b), "l"(c));
    return d;
}
__device__ __forceinline__ u64 pack2(float x, float y) {
    u64 r;
    asm("mov.b64 %0, {%1, %2};" : "=l"(r) : "f"(x), "f"(y));
    return r;
}
__device__ __forceinline__ void unpack2(u64 v, float& x, float& y) {
    asm("mov.b64 {%0, %1}, %2;" : "=f"(x), "=f"(y) : "l"(v));
}
__device__ __forceinline__ float sqrt_approx(float s) {
    float r;
    asm("sqrt.approx.f32 %0, %1;" : "=f"(r) : "f"(s));
    return r;
}

constexpr int ITER = 4;            // consecutive samples per thread
constexpr int TPB  = 128;
constexpr int SPB  = TPB * ITER;   // 512 (divides N = 2^20)
constexpr int TILE = SPB + 12;     // samples blockStart-5 .. +6
// pad(i) = i + (i>>2)
constexpr int PTILE = (TILE - 1) + ((TILE - 1) >> 2) + 1;

// coefficient slots (u64 {re,im}), 16B-aligned groups:
//   [0..3]    c0tot[l]                       (LDS.64 each)
//   [4..19]   E: l*4 + {e1,e2,e3,e4}        (2x LDS.128 per l)
//   [20..55]  B: poly*4 + {b1,b2,b3,pad}    poly = l*3+(m-1)  (LDS.128+LDS.64)
//   [56..91]  C: same layout
constexpr int NSLOT = 92;

__global__ __launch_bounds__(TPB, 9)
void gmp_kernel(const float* __restrict__ xre, const float* __restrict__ xim,
                const float* __restrict__ a_re, const float* __restrict__ a_im,
                const float* __restrict__ b_re, const float* __restrict__ b_im,
                const float* __restrict__ c_re, const float* __restrict__ c_im,
                float* __restrict__ out, int N) {
    __shared__ u64 sP[PTILE];                  // {p, p}   duplicated |x|
    __shared__ u64 sX[PTILE];                  // {re, im}
    __shared__ __align__(16) u64 scoef[NSLOT];

    const int tid = threadIdx.x;
    const int blockStart = blockIdx.x * SPB;

    // ---- per-block coefficient merge (threads 0..91), cheap one-time work
    if (tid < NSLOT) {
        float re = 0.f, im = 0.f;
        if (tid < 4) {                 // c0tot[l]
            int l = tid;
            re = a_re[l]; im = a_im[l];
            if (l < 3) {
#pragma unroll
                for (int m = 0; m < 4; ++m) {
                    re += b_re[l * 4 + m] + c_re[l * 4 + m];
                    im += b_im[l * 4 + m] + c_im[l * 4 + m];
                }
            }
        } else if (tid < 20) {         // E[l][k], k=1..4
            int e = tid - 4, l = e >> 2, k = (e & 3) + 1;
            re = a_re[k * 4 + l]; im = a_im[k * 4 + l];
            if (l < 3 && k < 4) {      // merge b/c m=0
                int src = (k * 3 + l) * 4;
                re += b_re[src] + c_re[src];
                im += b_im[src] + c_im[src];
            }
        } else if (tid < 56) {         // B: slot = 20 + poly*4 + s
            int e = tid - 20, poly = e >> 2, s = e & 3;
            if (s < 3) {
                int l = poly / 3, m = poly % 3 + 1, k = s + 1;
                int src = (k * 3 + l) * 4 + m;
                re = b_re[src]; im = b_im[src];
            }
        } else {                       // C: slot = 56 + poly*4 + s
            int e = tid - 56, poly = e >> 2, s = e & 3;
            if (s < 3) {
                int l = poly / 3, m = poly % 3 + 1, k = s + 1;
                int src = (k * 3 + l) * 4 + m;
                re = c_re[src]; im = c_im[src];
            }
        }
        scoef[tid] = pack2(re, im);
    }

    // ---- cooperative tile load: each sample once, |x| once, padded stores
#pragma unroll
    for (int s = tid; s < TILE; s += TPB) {
        int g = blockStart - 5 + s;
        g = max(g, 0);
        g = min(g, N - 1);
        float r = xre[g];
        float i = xim[g];
        float p = sqrt_approx(fmaf(r, r, i * i));
        int ps = s + (s >> 2);
        sX[ps] = pack2(r, i);
        sP[ps] = pack2(p, p);
    }
    __syncthreads();

    const int pb5 = tid * 5;            // pad(tid*4)
    const int n0 = blockStart + tid * ITER;

    // window j = 0..11 corresponds to sample n0 + j - 5; padded index:
#define PIDX(j) (pb5 + (j) + ((j) >> 2))

    // hot |x| sites j=1..10 in registers; j=0 and j=11 (single-use) from shared
    u64 ppr[10];
#pragma unroll
    for (int j = 1; j <= 10; ++j) ppr[j - 1] = sP[PIDX(j)];
#define GETP(j) (((j) >= 1 && (j) <= 10) ? ppr[(j) - 1] : sP[PIDX(j)])

    float yr[ITER], yi[ITER];
#pragma unroll
    for (int it = 0; it < ITER; ++it) { yr[it] = 0.f; yi[it] = 0.f; }

#pragma unroll
    for (int l = 0; l < 4; ++l) {
        u64 wl[ITER];
        {
            const u64 c0 = scoef[l];
#pragma unroll
            for (int it = 0; it < ITER; ++it) wl[it] = c0;
        }
        // E (deg 4): w += (((e4 p + e3) p + e2) p + e1) p   at p[n+it-l]
        {
            const ulonglong2 e12 = *reinterpret_cast<const ulonglong2*>(&scoef[4 + l * 4]);
            const ulonglong2 e34 = *reinterpret_cast<const ulonglong2*>(&scoef[4 + l * 4 + 2]);
#pragma unroll
            for (int it = 0; it < ITER; ++it) {
                const u64 p = GETP(it - l + 5);
                u64 q = fma2(e34.y, p, e34.x);
                q = fma2(q, p, e12.y);
                q = fma2(q, p, e12.x);
                wl[it] = fma2(q, p, wl[it]);
            }
        }
        if (l < 3) {
#pragma unroll
            for (int m = 1; m < 4; ++m) {   // B at p[n+it-l-m]
                const int bb = 20 + (l * 3 + (m - 1)) * 4;
                const ulonglong2 b12 = *reinterpret_cast<const ulonglong2*>(&scoef[bb]);
                const u64 b3 = scoef[bb + 2];
#pragma unroll
                for (int it = 0; it < ITER; ++it) {
                    const u64 p = GETP(it - l - m + 5);
                    u64 q = fma2(b3, p, b12.y);
                    q = fma2(q, p, b12.x);
                    wl[it] = fma2(q, p, wl[it]);
                }
            }
#pragma unroll
            for (int m = 1; m < 4; ++m) {   // C at p[n+it-l+m]
                const int cb = 56 + (l * 3 + (m - 1)) * 4;
                const ulonglong2 c12 = *reinterpret_cast<const ulonglong2*>(&scoef[cb]);
                const u64 c3 = scoef[cb + 2];
#pragma unroll
                for (int it = 0; it < ITER; ++it) {
                    const u64 p = GETP(it - l + m + 5);
                    u64 q = fma2(c3, p, c12.y);
                    q = fma2(q, p, c12.x);
                    wl[it] = fma2(q, p, wl[it]);
                }
            }
        }
        // combine: y[n+it] += x[n+it-l] * w_l   (complex; x from padded shared)
#pragma unroll
        for (int it = 0; it < ITER; ++it) {
            float vr, vi;
            unpack2(wl[it], vr, vi);
            float r, i;
            unpack2(sX[PIDX(it - l + 5)], r, i);
            yr[it] = fmaf(r, vr, yr[it]);
            yr[it] = fmaf(-i, vi, yr[it]);
            yi[it] = fmaf(r, vi, yi[it]);
            yi[it] = fmaf(i, vr, yi[it]);
        }
    }
#undef GETP
#undef PIDX

    // n0 multiple of 4 -> aligned float4 stores; SPB divides N
    if (n0 + ITER <= N) {
        *reinterpret_cast<float4*>(out + n0)     = make_float4(yr[0], yr[1], yr[2], yr[3]);
        *reinterpret_cast<float4*>(out + N + n0) = make_float4(yi[0], yi[1], yi[2], yi[3]);
    } else {
#pragma unroll
        for (int it = 0; it < ITER; ++it) {
            int n = n0 + it;
            if (n < N) { out[n] = yr[it]; out[N + n] = yi[it]; }
        }
    }
}

extern "C" void kernel_launch(void* const* d_in, const int* in_sizes, int n_in,
                              void* d_out, int out_size) {
    const float* x_re = (const float*)d_in[0];
    const float* x_im = (const float*)d_in[1];
    const float* a_re = (const float*)d_in[2];
    const float* a_im = (const float*)d_in[3];
    const float* b_re = (const float*)d_in[4];
    const float* b_im = (const float*)d_in[5];
    const float* c_re = (const float*)d_in[6];
    const float* c_im = (const float*)d_in[7];
    float* out = (float*)d_out;
    const int N = in_sizes[0];

    const int grid = (N + SPB - 1) / SPB;
    gmp_kernel<<<grid, TPB>>>(x_re, x_im, a_re, a_im, b_re, b_im,
                              c_re, c_im, out, N);
}

// round 16
// speedup vs baseline: 1.4168x; 1.2786x over previous
#include <cuda_runtime.h>
#include <cstdint>

// ---------------------------------------------------------------------------
// GMP_34196529611440 : generalized memory polynomial, single fused kernel.
// Round 14 = R8 config (ITER=4, TPB=256, natural 64 regs, occ-optimal) with
// issue-slot reduction:
//   * packed complex combine: Y1 = sum w*{r,r}, Y2 = sum w*{i,i}
//     -> y_re = Y1.lo - Y2.hi, y_im = Y2.lo + Y1.hi  (saves 24 fma slots +
//        16 MOVs per thread vs scalar complex multiply)
//   * coefficients in 16B-aligned groups, ld.shared.v2.u64 (56 -> 30 LDS)
//   * p-window registers = 10 multi-use sites only (j=0,11 single-use -> LDS)
// ---------------------------------------------------------------------------

typedef unsigned long long u64;

__device__ __forceinline__ u64 fma2(u64 a, u64 b, u64 c) {
    u64 d;
    asm("fma.rn.f32x2 %0, %1, %2, %3;" : "=l"(d) : "l"(a), "l"(b), "l"(c));
    return d;
}
__device__ __forceinline__ u64 pack2(float x, float y) {
    u64 r;
    asm("mov.b64 %0, {%1, %2};" : "=l"(r) : "f"(x), "f"(y));
    return r;
}
__device__ __forceinline__ void unpack2(u64 v, float& x, float& y) {
    asm("mov.b64 {%0, %1}, %2;" : "=f"(x), "=f"(y) : "l"(v));
}
__device__ __forceinline__ float sqrt_approx(float s) {
    float r;
    asm("sqrt.approx.f32 %0, %1;" : "=f"(r) : "f"(s));
    return r;
}

constexpr int ITER = 4;            // consecutive samples per thread
constexpr int TPB  = 256;
constexpr int SPB  = TPB * ITER;   // 1024 (divides N = 2^20)
constexpr int TILE = SPB + 12;     // samples blockStart-5 .. +6
// pad(i) = i + (i>>2): thread window stride 5 u64 -> conflict-free LDS.64
constexpr int PTILE = (TILE - 1) + ((TILE - 1) >> 2) + 1;

// coefficient slots (u64 {re,im}), 16B-aligned groups:
//   [0..3]    c0tot[l]
//   [4..19]   E: 4 + l*4 + {e1,e2,e3,e4}         (2x v2 per l)
//   [20..55]  B: 20 + poly*4 + {b1,b2,b3,pad}    poly = l*3+(m-1)
//   [56..91]  C: same layout
constexpr int NSLOT = 92;

__global__ __launch_bounds__(TPB, 4)
void gmp_kernel(const float* __restrict__ xre, const float* __restrict__ xim,
                const float* __restrict__ a_re, const float* __restrict__ a_im,
                const float* __restrict__ b_re, const float* __restrict__ b_im,
                const float* __restrict__ c_re, const float* __restrict__ c_im,
                float* __restrict__ out, int N) {
    __shared__ u64 sP[PTILE];                    // {p,  p }
    __shared__ u64 sRR[PTILE];                   // {re, re}
    __shared__ u64 sII[PTILE];                   // {im, im}
    __shared__ __align__(16) u64 scoef[NSLOT];

    const int tid = threadIdx.x;
    const int blockStart = blockIdx.x * SPB;

    // ---- per-block coefficient merge (threads 0..91), cheap one-time work
    if (tid < NSLOT) {
        float re = 0.f, im = 0.f;
        if (tid < 4) {                 // c0tot[l]
            int l = tid;
            re = a_re[l]; im = a_im[l];
            if (l < 3) {
#pragma unroll
                for (int m = 0; m < 4; ++m) {
                    re += b_re[l * 4 + m] + c_re[l * 4 + m];
                    im += b_im[l * 4 + m] + c_im[l * 4 + m];
                }
            }
        } else if (tid < 20) {         // E[l][k], k=1..4
            int e = tid - 4, l = e >> 2, k = (e & 3) + 1;
            re = a_re[k * 4 + l]; im = a_im[k * 4 + l];
            if (l < 3 && k < 4) {      // merge b/c m=0
                int src = (k * 3 + l) * 4;
                re += b_re[src] + c_re[src];
                im += b_im[src] + c_im[src];
            }
        } else if (tid < 56) {         // B: slot = 20 + poly*4 + s
            int e = tid - 20, poly = e >> 2, s = e & 3;
            if (s < 3) {
                int l = poly / 3, m = poly % 3 + 1, k = s + 1;
                int src = (k * 3 + l) * 4 + m;
                re = b_re[src]; im = b_im[src];
            }
        } else {                       // C: slot = 56 + poly*4 + s
            int e = tid - 56, poly = e >> 2, s = e & 3;
            if (s < 3) {
                int l = poly / 3, m = poly % 3 + 1, k = s + 1;
                int src = (k * 3 + l) * 4 + m;
                re = c_re[src]; im = c_im[src];
            }
        }
        scoef[tid] = pack2(re, im);
    }

    // ---- cooperative tile load: each sample once, |x| once, padded stores
#pragma unroll
    for (int s = tid; s < TILE; s += TPB) {
        int g = blockStart - 5 + s;
        g = max(g, 0);
        g = min(g, N - 1);
        float r = xre[g];
        float i = xim[g];
        float p = sqrt_approx(fmaf(r, r, i * i));
        int ps = s + (s >> 2);
        sP[ps]  = pack2(p, p);
        sRR[ps] = pack2(r, r);
        sII[ps] = pack2(i, i);
    }
    __syncthreads();

    const int pb5 = tid * 5;            // pad(tid*4)
    const int n0 = blockStart + tid * ITER;

    // window j = 0..11 corresponds to sample n0 + j - 5; padded index:
#define PIDX(j) (pb5 + (j) + ((j) >> 2))

    // hot |x| sites j=1..10 in registers; j=0 / j=11 are single-use -> shared
    u64 ppr[10];
#pragma unroll
    for (int j = 1; j <= 10; ++j) ppr[j - 1] = sP[PIDX(j)];
#define GETP(j) (((j) >= 1 && (j) <= 10) ? ppr[(j) - 1] : sP[PIDX(j)])

    // packed accumulators: Y1 = sum_l w_l*{r,r}, Y2 = sum_l w_l*{i,i}
    u64 Y1[ITER], Y2[ITER];
#pragma unroll
    for (int it = 0; it < ITER; ++it) { Y1[it] = 0ull; Y2[it] = 0ull; }

#pragma unroll
    for (int l = 0; l < 4; ++l) {
        u64 wl[ITER];
        {
            const u64 c0 = scoef[l];
#pragma unroll
            for (int it = 0; it < ITER; ++it) wl[it] = c0;
        }
        // E (deg 4): w += (((e4 p + e3) p + e2) p + e1) p   at p[n+it-l]
        {
            const ulonglong2 e12 = *reinterpret_cast<const ulonglong2*>(&scoef[4 + l * 4]);
            const ulonglong2 e34 = *reinterpret_cast<const ulonglong2*>(&scoef[4 + l * 4 + 2]);
#pragma unroll
            for (int it = 0; it < ITER; ++it) {
                const u64 p = GETP(it - l + 5);
                u64 q = fma2(e34.y, p, e34.x);
                q = fma2(q, p, e12.y);
                q = fma2(q, p, e12.x);
                wl[it] = fma2(q, p, wl[it]);
            }
        }
        if (l < 3) {
#pragma unroll
            for (int m = 1; m < 4; ++m) {   // B at p[n+it-l-m]
                const int bb = 20 + (l * 3 + (m - 1)) * 4;
                const ulonglong2 b12 = *reinterpret_cast<const ulonglong2*>(&scoef[bb]);
                const u64 b3 = scoef[bb + 2];
#pragma unroll
                for (int it = 0; it < ITER; ++it) {
                    const u64 p = GETP(it - l - m + 5);
                    u64 q = fma2(b3, p, b12.y);
                    q = fma2(q, p, b12.x);
                    wl[it] = fma2(q, p, wl[it]);
                }
            }
#pragma unroll
            for (int m = 1; m < 4; ++m) {   // C at p[n+it-l+m]
                const int cb = 56 + (l * 3 + (m - 1)) * 4;
                const ulonglong2 c12 = *reinterpret_cast<const ulonglong2*>(&scoef[cb]);
                const u64 c3 = scoef[cb + 2];
#pragma unroll
                for (int it = 0; it < ITER; ++it) {
                    const u64 p = GETP(it - l + m + 5);
                    u64 q = fma2(c3, p, c12.y);
                    q = fma2(q, p, c12.x);
                    wl[it] = fma2(q, p, wl[it]);
                }
            }
        }
        // combine: Y1 += w_l*{r,r}, Y2 += w_l*{i,i}  (packed; x from shared)
#pragma unroll
        for (int it = 0; it < ITER; ++it) {
            const int j = it - l + 5;
            Y1[it] = fma2(wl[it], sRR[PIDX(j)], Y1[it]);
            Y2[it] = fma2(wl[it], sII[PIDX(j)], Y2[it]);
        }
    }
#undef GETP
#undef PIDX

    // epilogue: y_re = Y1.lo - Y2.hi ; y_im = Y2.lo + Y1.hi
    float yr[ITER], yi[ITER];
#pragma unroll
    for (int it = 0; it < ITER; ++it) {
        float y1l, y1h, y2l, y2h;
        unpack2(Y1[it], y1l, y1h);
        unpack2(Y2[it], y2l, y2h);
        yr[it] = y1l - y2h;
        yi[it] = y2l + y1h;
    }

    // n0 multiple of 4 -> aligned float4 stores; SPB divides N
    if (n0 + ITER <= N) {
        *reinterpret_cast<float4*>(out + n0)     = make_float4(yr[0], yr[1], yr[2], yr[3]);
        *reinterpret_cast<float4*>(out + N + n0) = make_float4(yi[0], yi[1], yi[2], yi[3]);
    } else {
#pragma unroll
        for (int it = 0; it < ITER; ++it) {
            int n = n0 + it;
            if (n < N) { out[n] = yr[it]; out[N + n] = yi[it]; }
        }
    }
}

extern "C" void kernel_launch(void* const* d_in, const int* in_sizes, int n_in,
                              void* d_out, int out_size) {
    const float* x_re = (const float*)d_in[0];
    const float* x_im = (const float*)d_in[1];
    const float* a_re = (const float*)d_in[2];
    const float* a_im = (const float*)d_in[3];
    const float* b_re = (const float*)d_in[4];
    const float* b_im = (const float*)d_in[5];
    const float* c_re = (const float*)d_in[6];
    const float* c_im = (const float*)d_in[7];
    float* out = (float*)d_out;
    const int N = in_sizes[0];

    const int grid = (N + SPB - 1) / SPB;
    gmp_kernel<<<grid, TPB>>>(x_re, x_im, a_re, a_im, b_re, b_im,
                              c_re, c_im, out, N);
}